// round 15
// baseline (speedup 1.0000x reference)
#include <cuda_runtime.h>
#include <cuda_fp16.h>
#include <math.h>
#include <stdint.h>

#define T_   12
#define B_   16
#define N_   2048
#define D_   128
#define F_   1536
#define KTOP 5
#define NEG_SLOPE 0.01f
#define NCAND 8
#define DELTA 3.0e-4f

__device__ __half g_p1[(size_t)B_ * N_ * F_];
__device__ __half g_p2[(size_t)B_ * N_ * F_];
__device__ __half g_dist[(size_t)B_ * N_ * N_];   // fp16 Gram matrix (134 MB)

// ---------------------------------------------------------------------------
__device__ __forceinline__ uint32_t smem_u32(const void* p) {
    uint32_t a;
    asm("{ .reg .u64 t; cvta.to.shared.u64 t, %1; cvt.u32.u64 %0, t; }"
        : "=r"(a) : "l"(p));
    return a;
}
#define CP_ASYNC16(dst, src) \
    asm volatile("cp.async.cg.shared.global [%0], [%1], 16;" :: "r"(dst), "l"(src))
#define CP_COMMIT() asm volatile("cp.async.commit_group;")
#define CP_WAIT(n)  asm volatile("cp.async.wait_group %0;" :: "n"(n))

#define LDSM_X4(r, a)                                                          \
    asm volatile("ldmatrix.sync.aligned.m8n8.x4.shared.b16 {%0,%1,%2,%3}, [%4];" \
                 : "=r"((r)[0]), "=r"((r)[1]), "=r"((r)[2]), "=r"((r)[3])      \
                 : "r"(a))

#define MMA16816(acc, a, b0, b1)                                               \
    asm volatile(                                                              \
        "mma.sync.aligned.m16n8k16.row.col.f32.f16.f16.f32 "                   \
        "{%0,%1,%2,%3}, {%4,%5,%6,%7}, {%8,%9}, {%0,%1,%2,%3};"                \
        : "+f"((acc)[0]), "+f"((acc)[1]), "+f"((acc)[2]), "+f"((acc)[3])       \
        : "r"((a)[0]), "r"((a)[1]), "r"((a)[2]), "r"((a)[3]), "r"(b0), "r"(b1))

#define SW128(x) ((x) ^ (((x) >> 3) & 0x70))

typedef unsigned long long u64k;
__device__ __forceinline__ float key_val(u64k k) {
    unsigned u = (unsigned)(k >> 32);
    u = (u & 0x80000000u) ? (u & 0x7FFFFFFFu) : ~u;
    return __uint_as_float(u);
}
__device__ __forceinline__ int key_idx(u64k k) {
    return (int)(0xFFFFFFFFu - (unsigned)(k & 0xFFFFFFFFu));
}
__device__ __forceinline__ u64k mk_key(float v, int idx) {
    unsigned u = __float_as_uint(v);
    u = (u & 0x80000000u) ? ~u : (u | 0x80000000u);
    return ((u64k)u << 32) | (unsigned)(0xFFFFFFFFu - idx);
}
// 32-bit orderable value key (no NaN in data; 0 is a safe "popped" sentinel)
__device__ __forceinline__ unsigned o32(float v) {
    unsigned u = __float_as_uint(v);
    return (u & 0x80000000u) ? ~u : (u | 0x80000000u);
}
__device__ __forceinline__ unsigned redux_max_u32(unsigned v) {
    unsigned r;
    asm("redux.sync.max.u32 %0, %1, 0xffffffff;" : "=r"(r) : "r"(v));
    return r;
}
__device__ __forceinline__ unsigned redux_min_u32(unsigned v) {
    unsigned r;
    asm("redux.sync.min.u32 %0, %1, 0xffffffff;" : "=r"(r) : "r"(v));
    return r;
}

// ---------------------------------------------------------------------------
// K1: gather + normalize + fp16 split (proven)
// ---------------------------------------------------------------------------
__global__ __launch_bounds__(128) void pack_norm_kernel(const float* __restrict__ x) {
    int n = blockIdx.x, b = blockIdx.y, tid = threadIdx.x;
    int lane = tid & 31, wid = tid >> 5;
    float4 v[3];
    float ss = 0.f;
#pragma unroll
    for (int j = 0; j < 3; j++) {
        int idx4 = tid + j * 128;
        int t = idx4 >> 5, d4 = idx4 & 31;
        v[j] = *(const float4*)(x + (((size_t)t * B_ + b) * N_ + n) * D_ + d4 * 4);
        ss += v[j].x * v[j].x + v[j].y * v[j].y + v[j].z * v[j].z + v[j].w * v[j].w;
    }
    __shared__ float red[4];
#pragma unroll
    for (int o = 16; o; o >>= 1) ss += __shfl_xor_sync(0xffffffffu, ss, o);
    if (lane == 0) red[wid] = ss;
    __syncthreads();
    float r = rsqrtf(red[0] + red[1] + red[2] + red[3]);

    size_t base = ((size_t)b * N_ + n) * F_;
#pragma unroll
    for (int j = 0; j < 3; j++) {
        int idx4 = tid + j * 128;
        float a0 = v[j].x * r, a1 = v[j].y * r, a2 = v[j].z * r, a3 = v[j].w * r;
        __half h0 = __float2half_rn(a0), h1 = __float2half_rn(a1);
        __half h2 = __float2half_rn(a2), h3 = __float2half_rn(a3);
        *(__half2*)(g_p1 + base + idx4 * 4) = __halves2half2(h0, h1);
        *(__half2*)(g_p1 + base + idx4 * 4 + 2) = __halves2half2(h2, h3);
        *(__half2*)(g_p2 + base + idx4 * 4) =
            __halves2half2(__float2half_rn(a0 - __half2float(h0)),
                           __float2half_rn(a1 - __half2float(h1)));
        *(__half2*)(g_p2 + base + idx4 * 4 + 2) =
            __halves2half2(__float2half_rn(a2 - __half2float(h2)),
                           __float2half_rn(a3 - __half2float(h3)));
    }
}

// ---------------------------------------------------------------------------
// K2: symmetric Gram h1*h1^T, 3-stage cp.async pipeline + fused d_out zeroing.
// Epilogue stores fp16 dist.
// ---------------------------------------------------------------------------
#define NBLK   (N_ / 128)
#define NPAIR  (NBLK * (NBLK + 1) / 2)
#define SK     64
#define NS     (F_ / SK)
#define TILEB  (128 * 128)
#define STAGEB (2 * TILEB)
#define NSTAGE 3

__global__ __launch_bounds__(256, 2) void gemm_fp16_kernel(float* __restrict__ out,
                                                           size_t out_n4) {
    extern __shared__ __align__(16) unsigned char dynsmem[];
    uint32_t sraw = smem_u32(dynsmem);
    uint32_t bufb = (sraw + 1023) & ~1023u;

    int tid = threadIdx.x, lane = tid & 31, wid = tid >> 5;
    int p = blockIdx.x, b = blockIdx.y;
    int bi = 0, rem = p;
    while (rem >= NBLK - bi) { rem -= NBLK - bi; bi++; }
    int bj = bi + rem;

    size_t rowA = (size_t)b * N_ * F_ + (size_t)bi * 128 * F_;
    size_t rowB = (size_t)b * N_ * F_ + (size_t)bj * 128 * F_;

    int warp_row = wid & 1;
    int warp_col = wid >> 1;
    int lr = lane & 7, lm = lane >> 3;

    float acc[4][4][4];
#pragma unroll
    for (int mi = 0; mi < 4; mi++)
#pragma unroll
        for (int ni = 0; ni < 4; ni++)
#pragma unroll
            for (int r = 0; r < 4; r++) acc[mi][ni][r] = 0.f;

    auto load_stage = [&](int s, int buf) {
        int k0 = s * SK;
        const __half* Ap = g_p1 + rowA + k0;
        const __half* Bp = g_p1 + rowB + k0;
        uint32_t a_s = bufb + (uint32_t)buf * STAGEB;
        uint32_t b_s = a_s + TILEB;
#pragma unroll
        for (int t = 0; t < 4; t++) {
            int q = tid + t * 256;
            int r = q >> 3, c16 = q & 7;
            uint32_t so = SW128((uint32_t)(q << 4));
            size_t ge = (size_t)r * F_ + c16 * 8;
            CP_ASYNC16(a_s + so, Ap + ge);
            CP_ASYNC16(b_s + so, Bp + ge);
        }
    };

    load_stage(0, 0);
    CP_COMMIT();
    load_stage(1, 1);
    CP_COMMIT();

    int cbuf = 0, lbuf = 2;
#pragma unroll 1
    for (int s = 0; s < NS; s++) {
        if (s < NS - 1) CP_WAIT(1); else CP_WAIT(0);
        __syncthreads();
        if (s + 2 < NS) {
            load_stage(s + 2, lbuf);
            CP_COMMIT();
        }

        uint32_t a_s = bufb + (uint32_t)cbuf * STAGEB;
        uint32_t b_s = a_s + TILEB;

#pragma unroll
        for (int kc = 0; kc < 4; kc++) {
            int kb = kc * 32;
            uint32_t afr[4][4];
#pragma unroll
            for (int mi = 0; mi < 4; mi++) {
                int row = warp_row * 64 + mi * 16 + (lm & 1) * 8 + lr;
                int colb = kb + (lm >> 1) * 16;
                LDSM_X4(afr[mi], a_s + SW128((uint32_t)(row * 128 + colb)));
            }
            uint32_t bfr[2][4];
#pragma unroll
            for (int nj = 0; nj < 2; nj++) {
                int row = warp_col * 32 + nj * 16 + (lm >> 1) * 8 + lr;
                int colb = kb + (lm & 1) * 16;
                LDSM_X4(bfr[nj], b_s + SW128((uint32_t)(row * 128 + colb)));
            }
#pragma unroll
            for (int mi = 0; mi < 4; mi++)
#pragma unroll
                for (int ni = 0; ni < 4; ni++)
                    MMA16816(acc[mi][ni], afr[mi],
                             bfr[ni >> 1][(ni & 1) * 2],
                             bfr[ni >> 1][(ni & 1) * 2 + 1]);
        }

        cbuf = (cbuf == 2) ? 0 : cbuf + 1;
        lbuf = (lbuf == 2) ? 0 : lbuf + 1;
    }

    __half* Db = g_dist + (size_t)b * N_ * N_;
#pragma unroll
    for (int mi = 0; mi < 4; mi++) {
        int gi = bi * 128 + warp_row * 64 + mi * 16 + (lane >> 2);
#pragma unroll
        for (int ni = 0; ni < 4; ni++) {
            int noff = (ni >> 1) * 16 + (ni & 1) * 8;
            int gj = bj * 128 + warp_col * 32 + noff + 2 * (lane & 3);
            __half2 v01 = __floats2half2_rn(acc[mi][ni][0], acc[mi][ni][1]);
            __half2 v23 = __floats2half2_rn(acc[mi][ni][2], acc[mi][ni][3]);
            *(__half2*)&Db[(size_t)gi * N_ + gj] = v01;
            *(__half2*)&Db[(size_t)(gi + 8) * N_ + gj] = v23;
            if (bi != bj) {
                Db[(size_t)gj * N_ + gi] = __low2half(v01);
                Db[(size_t)(gj + 1) * N_ + gi] = __high2half(v01);
                Db[(size_t)gj * N_ + gi + 8] = __low2half(v23);
                Db[(size_t)(gj + 1) * N_ + gi + 8] = __high2half(v23);
            }
        }
    }

    // Fused zeroing of d_out (grid-stride float4 stores, coalesced)
    {
        size_t cta = (size_t)blockIdx.y * gridDim.x + blockIdx.x;
        size_t ncta = (size_t)gridDim.x * gridDim.y;
        float4 z = make_float4(0.f, 0.f, 0.f, 0.f);
        float4* o4 = (float4*)out;
        for (size_t q = cta * 256 + tid; q < out_n4; q += ncta * 256) o4[q] = z;
    }
}

// ---------------------------------------------------------------------------
// K3: block-per-row top-8 via redux.sync hierarchical selection (exact jax
// tie-break), gated warp-parallel exact rescore (exact values output when
// rescored; diagonal forced to 1.0), symmetric scatter.
// ---------------------------------------------------------------------------
#define CSWAP(a, b) \
    if (ck[a] < ck[b]) { u64k tk = ck[a]; ck[a] = ck[b]; ck[b] = tk; \
                         float tv = av[a]; av[a] = av[b]; av[b] = tv; }

__global__ __launch_bounds__(256) void topk_kernel(float* __restrict__ out) {
    int i = blockIdx.x, b = blockIdx.y, tid = threadIdx.x;
    int lane = tid & 31, wid = tid >> 5;
    const uint4* drow = (const uint4*)(g_dist + ((size_t)b * N_ + i) * N_);

    uint4 u = __ldg(&drow[tid]);  // 8 contiguous halfs: idx tid*8 .. tid*8+7
    unsigned ov[8];
    {
        __half2 h01 = *(__half2*)&u.x, h23 = *(__half2*)&u.y;
        __half2 h45 = *(__half2*)&u.z, h67 = *(__half2*)&u.w;
        ov[0] = o32(__low2float(h01));  ov[1] = o32(__high2float(h01));
        ov[2] = o32(__low2float(h23));  ov[3] = o32(__high2float(h23));
        ov[4] = o32(__low2float(h45));  ov[5] = o32(__high2float(h45));
        ov[6] = o32(__low2float(h67));  ov[7] = o32(__high2float(h67));
    }
    unsigned base0 = (unsigned)tid * 8;

    unsigned lmax = ov[0];
#pragma unroll
    for (int j = 1; j < 8; j++) lmax = lmax > ov[j] ? lmax : ov[j];

    __shared__ unsigned swv[64], swi[64];
    __shared__ u64k sfin[NCAND];
    __shared__ u64k newkey[NCAND];
    __shared__ float newval[NCAND];

    // Phase 1: per-warp top-8, lane r records round r. No barriers.
    unsigned rv = 0, ri = 0;
#pragma unroll
    for (int r = 0; r < 8; r++) {
        unsigned m = redux_max_u32(lmax);
        unsigned gi = 0xFFFFFFFFu;
#pragma unroll
        for (int j = 7; j >= 0; j--)
            if (ov[j] == m) gi = base0 + j;   // descending j: keeps lowest idx
        unsigned mi = redux_min_u32(gi);
        if (lane == r) { rv = m; ri = mi; }
        if (gi == mi) {                       // unique owner pops lowest match
            bool done = false;
#pragma unroll
            for (int j = 0; j < 8; j++)
                if (!done && ov[j] == m) { ov[j] = 0; done = true; }
            lmax = ov[0];
#pragma unroll
            for (int j = 1; j < 8; j++) lmax = lmax > ov[j] ? lmax : ov[j];
        }
    }
    if (lane < 8) { swv[wid * 8 + lane] = rv; swi[wid * 8 + lane] = ri; }
    __syncthreads();

    // Phase 2: warp 0 merges 64 candidates (2 per lane)
    if (wid == 0) {
        unsigned c0v = swv[lane], c0i = swi[lane];
        unsigned c1v = swv[lane + 32], c1i = swi[lane + 32];
        unsigned lm2 = c0v > c1v ? c0v : c1v;
        unsigned fv = 0, fi = 0;
#pragma unroll
        for (int r = 0; r < 8; r++) {
            unsigned m = redux_max_u32(lm2);
            unsigned gi = 0xFFFFFFFFu;
            if (c1v == m) gi = c1i;
            if (c0v == m) gi = c0i < gi ? c0i : gi;
            unsigned mi = redux_min_u32(gi);
            if (lane == r) { fv = m; fi = mi; }
            if (gi == mi) {
                if (c0v == m && c0i == mi) c0v = 0; else c1v = 0;
                lm2 = c0v > c1v ? c0v : c1v;
            }
        }
        if (lane < 8) sfin[lane] = ((u64k)fv << 32) | (0xFFFFFFFFu - fi);
    }
    __syncthreads();

    u64k ck[NCAND];
    float av[NCAND];
#pragma unroll
    for (int c = 0; c < NCAND; c++) { ck[c] = sfin[c]; av[c] = key_val(ck[c]); }

    // gate (identical on all threads)
    float v5 = av[4];
    bool need = false;
#pragma unroll
    for (int c = 0; c < NCAND; c++)
        if (c != 4 && fabsf(av[c] - v5) < DELTA) need = true;

    if (need) {
        if (lane == 0) { newkey[wid] = ck[wid]; newval[wid] = av[wid]; }
        bool inwin = (wid == 4) || (fabsf(av[wid] - v5) < DELTA);
        if (inwin) {
            int j = key_idx(ck[wid]);
            size_t basei = ((size_t)b * N_ + i) * F_;
            size_t basej = ((size_t)b * N_ + j) * F_;
            float acc = 0.f;
#pragma unroll
            for (int s = 0; s < 48; s++) {
                int e = s * 32 + lane;
                float fi2 = __half2float(g_p1[basei + e]) + __half2float(g_p2[basei + e]);
                float fj2 = __half2float(g_p1[basej + e]) + __half2float(g_p2[basej + e]);
                acc = fmaf(fi2, fj2, acc);
            }
#pragma unroll
            for (int o = 16; o; o >>= 1) acc += __shfl_xor_sync(0xffffffffu, acc, o);
            if (lane == 0) { newkey[wid] = mk_key(acc, j); newval[wid] = acc; }
        }
        __syncthreads();
#pragma unroll
        for (int c = 0; c < NCAND; c++) { ck[c] = newkey[c]; av[c] = newval[c]; }
        CSWAP(0, 1) CSWAP(2, 3) CSWAP(4, 5) CSWAP(6, 7)
        CSWAP(0, 2) CSWAP(1, 3) CSWAP(4, 6) CSWAP(5, 7)
        CSWAP(1, 2) CSWAP(5, 6)
        CSWAP(0, 4) CSWAP(1, 5) CSWAP(2, 6) CSWAP(3, 7)
        CSWAP(2, 4) CSWAP(3, 5)
        CSWAP(1, 2) CSWAP(3, 4) CSWAP(5, 6)
    }

    if (tid < KTOP) {
        float val = av[tid];
        int j = key_idx(ck[tid]);
        if (j == i) val = 1.0f;  // reference diag = ||xn||^2 = 1 +/- 1e-6
        float w = 0.5f * (val >= 0.f ? val : NEG_SLOPE * val);
        float* ob = out + (size_t)b * N_ * N_;
        atomicAdd(&ob[(size_t)i * N_ + j], w);
        atomicAdd(&ob[(size_t)j * N_ + i], w);
    }
}

// ---------------------------------------------------------------------------
extern "C" void kernel_launch(void* const* d_in, const int* in_sizes, int n_in,
                              void* d_out, int out_size) {
    const float* x = (const float*)d_in[0];
    float* out = (float*)d_out;

    const int SMEM_DYN = 1024 + NSTAGE * STAGEB;
    cudaFuncSetAttribute(gemm_fp16_kernel,
                         cudaFuncAttributeMaxDynamicSharedMemorySize, SMEM_DYN);

    pack_norm_kernel<<<dim3(N_, B_), 128>>>(x);
    gemm_fp16_kernel<<<dim3(NPAIR, B_), 256, SMEM_DYN>>>(out, (size_t)out_size / 4);
    topk_kernel<<<dim3(N_, B_), 256>>>(out);
}

// round 16
// speedup vs baseline: 1.1004x; 1.1004x over previous
#include <cuda_runtime.h>
#include <cuda_fp16.h>
#include <math.h>
#include <stdint.h>

#define T_   12
#define B_   16
#define N_   2048
#define D_   128
#define F_   1536
#define KTOP 5
#define NEG_SLOPE 0.01f
#define NCAND 8
#define DELTA 1.2e-4f

__device__ __half g_p1[(size_t)B_ * N_ * F_];
__device__ float g_rnorm[(size_t)B_ * N_];
__device__ float g_dist[(size_t)B_ * N_ * N_];

// ---------------------------------------------------------------------------
__device__ __forceinline__ uint32_t smem_u32(const void* p) {
    uint32_t a;
    asm("{ .reg .u64 t; cvta.to.shared.u64 t, %1; cvt.u32.u64 %0, t; }"
        : "=r"(a) : "l"(p));
    return a;
}
#define CP_ASYNC16(dst, src) \
    asm volatile("cp.async.cg.shared.global [%0], [%1], 16;" :: "r"(dst), "l"(src))
#define CP_COMMIT() asm volatile("cp.async.commit_group;")
#define CP_WAIT(n)  asm volatile("cp.async.wait_group %0;" :: "n"(n))

#define LDSM_X4(r, a)                                                          \
    asm volatile("ldmatrix.sync.aligned.m8n8.x4.shared.b16 {%0,%1,%2,%3}, [%4];" \
                 : "=r"((r)[0]), "=r"((r)[1]), "=r"((r)[2]), "=r"((r)[3])      \
                 : "r"(a))

#define MMA16816(acc, a, b0, b1)                                               \
    asm volatile(                                                              \
        "mma.sync.aligned.m16n8k16.row.col.f32.f16.f16.f32 "                   \
        "{%0,%1,%2,%3}, {%4,%5,%6,%7}, {%8,%9}, {%0,%1,%2,%3};"                \
        : "+f"((acc)[0]), "+f"((acc)[1]), "+f"((acc)[2]), "+f"((acc)[3])       \
        : "r"((a)[0]), "r"((a)[1]), "r"((a)[2]), "r"((a)[3]), "r"(b0), "r"(b1))

#define SW128(x) ((x) ^ (((x) >> 3) & 0x70))

typedef unsigned long long u64k;
__device__ __forceinline__ float key_val(u64k k) {
    unsigned u = (unsigned)(k >> 32);
    u = (u & 0x80000000u) ? (u & 0x7FFFFFFFu) : ~u;
    return __uint_as_float(u);
}
__device__ __forceinline__ int key_idx(u64k k) {
    return (int)(0xFFFFFFFFu - (unsigned)(k & 0xFFFFFFFFu));
}
__device__ __forceinline__ u64k mk_key(float v, int idx) {
    unsigned u = __float_as_uint(v);
    u = (u & 0x80000000u) ? ~u : (u | 0x80000000u);
    return ((u64k)u << 32) | (unsigned)(0xFFFFFFFFu - idx);
}
__device__ __forceinline__ unsigned o32(float v) {
    unsigned u = __float_as_uint(v);
    return (u & 0x80000000u) ? ~u : (u | 0x80000000u);
}
__device__ __forceinline__ unsigned redux_max_u32(unsigned v) {
    unsigned r;
    asm("redux.sync.max.u32 %0, %1, 0xffffffff;" : "=r"(r) : "r"(v));
    return r;
}
__device__ __forceinline__ unsigned redux_min_u32(unsigned v) {
    unsigned r;
    asm("redux.sync.min.u32 %0, %1, 0xffffffff;" : "=r"(r) : "r"(v));
    return r;
}

// ---------------------------------------------------------------------------
// K1: gather + normalize + fp16 h1 (g_p2 eliminated; rnorm stored for rescore)
// ---------------------------------------------------------------------------
__global__ __launch_bounds__(128) void pack_norm_kernel(const float* __restrict__ x) {
    int n = blockIdx.x, b = blockIdx.y, tid = threadIdx.x;
    int lane = tid & 31, wid = tid >> 5;
    float4 v[3];
    float ss = 0.f;
#pragma unroll
    for (int j = 0; j < 3; j++) {
        int idx4 = tid + j * 128;
        int t = idx4 >> 5, d4 = idx4 & 31;
        v[j] = *(const float4*)(x + (((size_t)t * B_ + b) * N_ + n) * D_ + d4 * 4);
        ss += v[j].x * v[j].x + v[j].y * v[j].y + v[j].z * v[j].z + v[j].w * v[j].w;
    }
    __shared__ float red[4];
#pragma unroll
    for (int o = 16; o; o >>= 1) ss += __shfl_xor_sync(0xffffffffu, ss, o);
    if (lane == 0) red[wid] = ss;
    __syncthreads();
    float r = rsqrtf(red[0] + red[1] + red[2] + red[3]);
    if (tid == 0) g_rnorm[(size_t)b * N_ + n] = r;

    size_t base = ((size_t)b * N_ + n) * F_;
#pragma unroll
    for (int j = 0; j < 3; j++) {
        int idx4 = tid + j * 128;
        float a0 = v[j].x * r, a1 = v[j].y * r, a2 = v[j].z * r, a3 = v[j].w * r;
        *(__half2*)(g_p1 + base + idx4 * 4) =
            __halves2half2(__float2half_rn(a0), __float2half_rn(a1));
        *(__half2*)(g_p1 + base + idx4 * 4 + 2) =
            __halves2half2(__float2half_rn(a2), __float2half_rn(a3));
    }
}

// ---------------------------------------------------------------------------
// K2: symmetric Gram h1*h1^T, 3-stage cp.async pipeline + fused d_out zeroing
// (proven R14)
// ---------------------------------------------------------------------------
#define NBLK   (N_ / 128)
#define NPAIR  (NBLK * (NBLK + 1) / 2)
#define SK     64
#define NS     (F_ / SK)
#define TILEB  (128 * 128)
#define STAGEB (2 * TILEB)
#define NSTAGE 3

__global__ __launch_bounds__(256, 2) void gemm_fp16_kernel(float* __restrict__ out,
                                                           size_t out_n4) {
    extern __shared__ __align__(16) unsigned char dynsmem[];
    uint32_t sraw = smem_u32(dynsmem);
    uint32_t bufb = (sraw + 1023) & ~1023u;

    int tid = threadIdx.x, lane = tid & 31, wid = tid >> 5;
    int p = blockIdx.x, b = blockIdx.y;
    int bi = 0, rem = p;
    while (rem >= NBLK - bi) { rem -= NBLK - bi; bi++; }
    int bj = bi + rem;

    size_t rowA = (size_t)b * N_ * F_ + (size_t)bi * 128 * F_;
    size_t rowB = (size_t)b * N_ * F_ + (size_t)bj * 128 * F_;

    int warp_row = wid & 1;
    int warp_col = wid >> 1;
    int lr = lane & 7, lm = lane >> 3;

    float acc[4][4][4];
#pragma unroll
    for (int mi = 0; mi < 4; mi++)
#pragma unroll
        for (int ni = 0; ni < 4; ni++)
#pragma unroll
            for (int r = 0; r < 4; r++) acc[mi][ni][r] = 0.f;

    auto load_stage = [&](int s, int buf) {
        int k0 = s * SK;
        const __half* Ap = g_p1 + rowA + k0;
        const __half* Bp = g_p1 + rowB + k0;
        uint32_t a_s = bufb + (uint32_t)buf * STAGEB;
        uint32_t b_s = a_s + TILEB;
#pragma unroll
        for (int t = 0; t < 4; t++) {
            int q = tid + t * 256;
            int r = q >> 3, c16 = q & 7;
            uint32_t so = SW128((uint32_t)(q << 4));
            size_t ge = (size_t)r * F_ + c16 * 8;
            CP_ASYNC16(a_s + so, Ap + ge);
            CP_ASYNC16(b_s + so, Bp + ge);
        }
    };

    load_stage(0, 0);
    CP_COMMIT();
    load_stage(1, 1);
    CP_COMMIT();

    int cbuf = 0, lbuf = 2;
#pragma unroll 1
    for (int s = 0; s < NS; s++) {
        if (s < NS - 1) CP_WAIT(1); else CP_WAIT(0);
        __syncthreads();
        if (s + 2 < NS) {
            load_stage(s + 2, lbuf);
            CP_COMMIT();
        }

        uint32_t a_s = bufb + (uint32_t)cbuf * STAGEB;
        uint32_t b_s = a_s + TILEB;

#pragma unroll
        for (int kc = 0; kc < 4; kc++) {
            int kb = kc * 32;
            uint32_t afr[4][4];
#pragma unroll
            for (int mi = 0; mi < 4; mi++) {
                int row = warp_row * 64 + mi * 16 + (lm & 1) * 8 + lr;
                int colb = kb + (lm >> 1) * 16;
                LDSM_X4(afr[mi], a_s + SW128((uint32_t)(row * 128 + colb)));
            }
            uint32_t bfr[2][4];
#pragma unroll
            for (int nj = 0; nj < 2; nj++) {
                int row = warp_col * 32 + nj * 16 + (lm >> 1) * 8 + lr;
                int colb = kb + (lm & 1) * 16;
                LDSM_X4(bfr[nj], b_s + SW128((uint32_t)(row * 128 + colb)));
            }
#pragma unroll
            for (int mi = 0; mi < 4; mi++)
#pragma unroll
                for (int ni = 0; ni < 4; ni++)
                    MMA16816(acc[mi][ni], afr[mi],
                             bfr[ni >> 1][(ni & 1) * 2],
                             bfr[ni >> 1][(ni & 1) * 2 + 1]);
        }

        cbuf = (cbuf == 2) ? 0 : cbuf + 1;
        lbuf = (lbuf == 2) ? 0 : lbuf + 1;
    }

    float* Db = g_dist + (size_t)b * N_ * N_;
#pragma unroll
    for (int mi = 0; mi < 4; mi++) {
        int gi = bi * 128 + warp_row * 64 + mi * 16 + (lane >> 2);
#pragma unroll
        for (int ni = 0; ni < 4; ni++) {
            int noff = (ni >> 1) * 16 + (ni & 1) * 8;
            int gj = bj * 128 + warp_col * 32 + noff + 2 * (lane & 3);
            float2 v01 = make_float2(acc[mi][ni][0], acc[mi][ni][1]);
            float2 v23 = make_float2(acc[mi][ni][2], acc[mi][ni][3]);
            *(float2*)&Db[(size_t)gi * N_ + gj] = v01;
            *(float2*)&Db[(size_t)(gi + 8) * N_ + gj] = v23;
            if (bi != bj) {
                Db[(size_t)gj * N_ + gi] = v01.x;
                Db[(size_t)(gj + 1) * N_ + gi] = v01.y;
                Db[(size_t)gj * N_ + gi + 8] = v23.x;
                Db[(size_t)(gj + 1) * N_ + gi + 8] = v23.y;
            }
        }
    }

    // Fused zeroing of d_out (grid-stride float4 stores, coalesced)
    {
        size_t cta = (size_t)blockIdx.y * gridDim.x + blockIdx.x;
        size_t ncta = (size_t)gridDim.x * gridDim.y;
        float4 z = make_float4(0.f, 0.f, 0.f, 0.f);
        float4* o4 = (float4*)out;
        for (size_t q = cta * 256 + tid; q < out_n4; q += ncta * 256) o4[q] = z;
    }
}

// ---------------------------------------------------------------------------
// K3: block-per-row top-8 via redux.sync hierarchical selection (proven R14),
// gated warp-parallel exact rescore FROM fp32 x (+ stored rnorms), scatter.
// ---------------------------------------------------------------------------
#define CSWAP(a, b) \
    if (ck[a] < ck[b]) { u64k tk = ck[a]; ck[a] = ck[b]; ck[b] = tk; \
                         float tv = av[a]; av[a] = av[b]; av[b] = tv; }

__global__ __launch_bounds__(256) void topk_kernel(const float* __restrict__ x,
                                                   float* __restrict__ out) {
    int i = blockIdx.x, b = blockIdx.y, tid = threadIdx.x;
    int lane = tid & 31, wid = tid >> 5;
    const float4* drow4 = (const float4*)(g_dist + ((size_t)b * N_ + i) * N_);

    float4 va = __ldg(&drow4[tid]);
    float4 vb = __ldg(&drow4[tid + 256]);
    unsigned ov[8];
    ov[0] = o32(va.x); ov[1] = o32(va.y); ov[2] = o32(va.z); ov[3] = o32(va.w);
    ov[4] = o32(vb.x); ov[5] = o32(vb.y); ov[6] = o32(vb.z); ov[7] = o32(vb.w);
    unsigned base0 = (unsigned)tid * 4;  // slot j: j<4 -> base0+j ; j>=4 -> base0+1020+j

    unsigned lmax = ov[0];
#pragma unroll
    for (int j = 1; j < 8; j++) lmax = lmax > ov[j] ? lmax : ov[j];

    __shared__ unsigned swv[64], swi[64];
    __shared__ u64k sfin[NCAND];
    __shared__ u64k newkey[NCAND];
    __shared__ float newval[NCAND];

    // Phase 1: per-warp top-8, lane r records round r. No barriers.
    unsigned rv = 0, ri = 0;
#pragma unroll
    for (int r = 0; r < 8; r++) {
        unsigned m = redux_max_u32(lmax);
        unsigned gi = 0xFFFFFFFFu;
#pragma unroll
        for (int j = 7; j >= 0; j--) {
            unsigned e = (j < 4) ? (base0 + j) : (base0 + 1020 + j);
            if (ov[j] == m) gi = e;   // descending j: keeps lowest elem idx
        }
        unsigned mi = redux_min_u32(gi);
        if (lane == r) { rv = m; ri = mi; }
        if (gi == mi) {               // unique owner pops its lowest matching slot
            bool done = false;
#pragma unroll
            for (int j = 0; j < 8; j++)
                if (!done && ov[j] == m) { ov[j] = 0; done = true; }
            lmax = ov[0];
#pragma unroll
            for (int j = 1; j < 8; j++) lmax = lmax > ov[j] ? lmax : ov[j];
        }
    }
    if (lane < 8) { swv[wid * 8 + lane] = rv; swi[wid * 8 + lane] = ri; }
    __syncthreads();

    // Phase 2: warp 0 merges 64 candidates (2 per lane)
    if (wid == 0) {
        unsigned c0v = swv[lane], c0i = swi[lane];
        unsigned c1v = swv[lane + 32], c1i = swi[lane + 32];
        unsigned lm2 = c0v > c1v ? c0v : c1v;
        unsigned fv = 0, fi = 0;
#pragma unroll
        for (int r = 0; r < 8; r++) {
            unsigned m = redux_max_u32(lm2);
            unsigned gi = 0xFFFFFFFFu;
            if (c1v == m) gi = c1i;
            if (c0v == m) gi = c0i < gi ? c0i : gi;
            unsigned mi = redux_min_u32(gi);
            if (lane == r) { fv = m; fi = mi; }
            if (gi == mi) {
                if (c0v == m && c0i == mi) c0v = 0; else c1v = 0;
                lm2 = c0v > c1v ? c0v : c1v;
            }
        }
        if (lane < 8) sfin[lane] = ((u64k)fv << 32) | (0xFFFFFFFFu - fi);
    }
    __syncthreads();

    u64k ck[NCAND];
    float av[NCAND];
#pragma unroll
    for (int c = 0; c < NCAND; c++) { ck[c] = sfin[c]; av[c] = key_val(ck[c]); }

    // gate (identical on all threads)
    float v5 = av[4];
    bool need = false;
#pragma unroll
    for (int c = 0; c < NCAND; c++)
        if (c != 4 && fabsf(av[c] - v5) < DELTA) need = true;

    if (need) {
        if (lane == 0) { newkey[wid] = ck[wid]; newval[wid] = av[wid]; }
        bool inwin = (wid == 4) || (fabsf(av[wid] - v5) < DELTA);
        if (inwin) {
            int j = key_idx(ck[wid]);
            float rn = g_rnorm[(size_t)b * N_ + i] * g_rnorm[(size_t)b * N_ + j];
            float acc = 0.f;
#pragma unroll
            for (int s = 0; s < 48; s++) {
                int e = s * 32 + lane;
                int t = e >> 7, d = e & 127;
                size_t off = (((size_t)t * B_ + b) * N_) * D_ + d;
                float xi = __ldg(x + off + (size_t)i * D_);
                float xj = __ldg(x + off + (size_t)j * D_);
                acc = fmaf(xi, xj, acc);
            }
#pragma unroll
            for (int o = 16; o; o >>= 1) acc += __shfl_xor_sync(0xffffffffu, acc, o);
            float ex = acc * rn;
            if (lane == 0) { newkey[wid] = mk_key(ex, j); newval[wid] = ex; }
        }
        __syncthreads();
#pragma unroll
        for (int c = 0; c < NCAND; c++) { ck[c] = newkey[c]; av[c] = newval[c]; }
        CSWAP(0, 1) CSWAP(2, 3) CSWAP(4, 5) CSWAP(6, 7)
        CSWAP(0, 2) CSWAP(1, 3) CSWAP(4, 6) CSWAP(5, 7)
        CSWAP(1, 2) CSWAP(5, 6)
        CSWAP(0, 4) CSWAP(1, 5) CSWAP(2, 6) CSWAP(3, 7)
        CSWAP(2, 4) CSWAP(3, 5)
        CSWAP(1, 2) CSWAP(3, 4) CSWAP(5, 6)
    }

    if (tid < KTOP) {
        float val = av[tid];
        int j = key_idx(ck[tid]);
        if (j == i) val = 1.0f;  // reference diag = ||xn||^2 = 1 +/- 1e-7
        float w = 0.5f * (val >= 0.f ? val : NEG_SLOPE * val);
        float* ob = out + (size_t)b * N_ * N_;
        atomicAdd(&ob[(size_t)i * N_ + j], w);
        atomicAdd(&ob[(size_t)j * N_ + i], w);
    }
}

// ---------------------------------------------------------------------------
extern "C" void kernel_launch(void* const* d_in, const int* in_sizes, int n_in,
                              void* d_out, int out_size) {
    const float* x = (const float*)d_in[0];
    float* out = (float*)d_out;

    const int SMEM_DYN = 1024 + NSTAGE * STAGEB;
    cudaFuncSetAttribute(gemm_fp16_kernel,
                         cudaFuncAttributeMaxDynamicSharedMemorySize, SMEM_DYN);

    pack_norm_kernel<<<dim3(N_, B_), 128>>>(x);
    gemm_fp16_kernel<<<dim3(NPAIR, B_), 256, SMEM_DYN>>>(out, (size_t)out_size / 4);
    topk_kernel<<<dim3(N_, B_), 256>>>(x, out);
}